// round 6
// baseline (speedup 1.0000x reference)
#include <cuda_runtime.h>

// Problem constants
#define BB   32
#define QHH  32
#define KVHH 8
#define DD   128
#define PP   4096
#define NN   4096       // QHH*DD
#define KNN  1024       // KVHH*DD
#define GG   4          // QHH/KVHH
#define ROWS_TOT 6144   // NN + 2*KNN
#define KSPLIT 8
#define NCHUNK 4
#define SROW (KVHH*DD)  // 1024 floats stride over s in cache

// Scratch (device globals; no allocations allowed)
__device__ float g_xnorm[BB * NN];                       // 512 KB
__device__ float g_gpart[KSPLIT][BB * ROWS_TOT];        // 6 MB
__device__ float g_qkv[BB * ROWS_TOT];                  // 768 KB
__device__ float g_pnum[BB * KVHH * NCHUNK][GG * DD];   // 2 MB
__device__ float g_pden[BB * KVHH * NCHUNK][GG];        // 16 KB

// ---------------------------------------------------------------------------
// 1) RMSNorm: x_norm = X / sqrt(mean(X^2))   (one block per batch row)
// ---------------------------------------------------------------------------
__global__ void rms_kernel(const float* __restrict__ X) {
    int b = blockIdx.x;
    int t = threadIdx.x;  // 256
    const float4* x4 = (const float4*)(X + (size_t)b * NN);
    float ss = 0.f;
    for (int i = t; i < NN / 4; i += 256) {
        float4 a = x4[i];
        ss += a.x * a.x + a.y * a.y + a.z * a.z + a.w * a.w;
    }
    __shared__ float red[256];
    red[t] = ss;
    __syncthreads();
    for (int o = 128; o > 0; o >>= 1) {
        if (t < o) red[t] += red[t + o];
        __syncthreads();
    }
    float scale = rsqrtf(red[0] / (float)NN);
    float4* o4 = (float4*)(g_xnorm + (size_t)b * NN);
    for (int i = t; i < NN / 4; i += 256) {
        float4 a = x4[i];
        a.x *= scale; a.y *= scale; a.z *= scale; a.w *= scale;
        o4[i] = a;
    }
}

// ---------------------------------------------------------------------------
// 2) QKV projection: out[b][r] = dot(x_norm[b], W[r])  for combined rows
//    r in [0,4096) -> Wq, [4096,5120) -> Wk, [5120,6144) -> Wv
//    K-split over 8 for occupancy; partials reduced deterministically.
// ---------------------------------------------------------------------------
#define TKC 64
__global__ void qkv_kernel(const float* __restrict__ Wq,
                           const float* __restrict__ Wk,
                           const float* __restrict__ Wv) {
    int rtile = blockIdx.x;   // 0..47
    int ks    = blockIdx.y;   // 0..7
    int tid   = threadIdx.x;  // 256
    int r0 = rtile * 128;
    const float* Wbase;
    if (r0 < NN)            Wbase = Wq + (size_t)r0 * NN;
    else if (r0 < NN + KNN) Wbase = Wk + (size_t)(r0 - NN) * NN;
    else                    Wbase = Wv + (size_t)(r0 - NN - KNN) * NN;
    int k0 = ks * (NN / KSPLIT);  // 512-wide K slice

    __shared__ __align__(16) float xs[BB][TKC];
    __shared__ float ws[128][TKC + 1];

    int rq = tid & 31;   // row lane
    int bq = tid >> 5;   // 0..7 -> batch group of 4

    float acc[4][4];
#pragma unroll
    for (int i = 0; i < 4; i++)
#pragma unroll
        for (int j = 0; j < 4; j++) acc[i][j] = 0.f;

    for (int kc = 0; kc < NN / KSPLIT; kc += TKC) {
        // load x tile: 32 x 64 floats
        for (int idx = tid; idx < BB * (TKC / 4); idx += 256) {
            int bb = idx / (TKC / 4), c4 = idx % (TKC / 4);
            float4 v = *(const float4*)(g_xnorm + (size_t)bb * NN + k0 + kc + c4 * 4);
            *(float4*)&xs[bb][c4 * 4] = v;
        }
        // load W tile: 128 x 64 floats (padded rows)
        for (int idx = tid; idx < 128 * (TKC / 4); idx += 256) {
            int r = idx / (TKC / 4), c4 = idx % (TKC / 4);
            float4 v = *(const float4*)(Wbase + (size_t)r * NN + k0 + kc + c4 * 4);
            ws[r][c4 * 4 + 0] = v.x;
            ws[r][c4 * 4 + 1] = v.y;
            ws[r][c4 * 4 + 2] = v.z;
            ws[r][c4 * 4 + 3] = v.w;
        }
        __syncthreads();
#pragma unroll 8
        for (int k = 0; k < TKC; k++) {
            float xv[4], wv[4];
#pragma unroll
            for (int i = 0; i < 4; i++) xv[i] = xs[bq * 4 + i][k];   // broadcast
#pragma unroll
            for (int j = 0; j < 4; j++) wv[j] = ws[rq + 32 * j][k];  // conflict-free
#pragma unroll
            for (int i = 0; i < 4; i++)
#pragma unroll
                for (int j = 0; j < 4; j++) acc[i][j] += xv[i] * wv[j];
        }
        __syncthreads();
    }
#pragma unroll
    for (int i = 0; i < 4; i++) {
        int bb = bq * 4 + i;
#pragma unroll
        for (int j = 0; j < 4; j++) {
            int r = r0 + rq + 32 * j;
            g_gpart[ks][(size_t)bb * ROWS_TOT + r] = acc[i][j];
        }
    }
}

__global__ void qkv_reduce() {
    int idx = blockIdx.x * 256 + threadIdx.x;  // B*ROWS_TOT total
    float s = 0.f;
#pragma unroll
    for (int ks = 0; ks < KSPLIT; ks++) s += g_gpart[ks][idx];
    g_qkv[idx] = s;
}

// ---------------------------------------------------------------------------
// 3) Split-KV attention. Non-stabilized softmax is linear across S-partitions:
//    each block (b, kvh, chunk) accumulates partial (sum e, sum e*v).
//    Phase A: thread = KV row (scores + exp). Phase B: thread = head dim
//    (coalesced V accumulation). Appended k_new/v_new row handled in chunk 3.
// ---------------------------------------------------------------------------
__global__ void attn_kernel(const float* __restrict__ cK,
                            const float* __restrict__ cV) {
    int c   = blockIdx.x;   // chunk 0..3
    int kvh = blockIdx.y;   // 0..7
    int b   = blockIdx.z;   // 0..31
    int t   = threadIdx.x;  // 128

    __shared__ __align__(16) float qs[GG][DD];
    __shared__ __align__(16) float Es[GG][128];
    __shared__ float sred[GG][128];

    for (int i = t; i < GG * DD; i += 128) {
        int g = i >> 7, d = i & 127;
        qs[g][d] = g_qkv[(size_t)b * ROWS_TOT + (kvh * GG + g) * DD + d];
    }
    __syncthreads();

    float O[GG]    = {0.f, 0.f, 0.f, 0.f};
    float dent[GG] = {0.f, 0.f, 0.f, 0.f};
    const size_t baseK = ((size_t)b * PP) * SROW + (size_t)kvh * DD;

    for (int t0 = c * 1024; t0 < c * 1024 + 1024; t0 += 128) {
        int s = t0 + t;
        // ---- Phase A: per-thread row scores ----
        const float4* K4 = (const float4*)(cK + baseK + (size_t)s * SROW);
        float sc0 = 0.f, sc1 = 0.f, sc2 = 0.f, sc3 = 0.f;
#pragma unroll 8
        for (int d4 = 0; d4 < DD / 4; d4++) {
            float4 k  = K4[d4];
            float4 q0 = *(const float4*)&qs[0][d4 * 4];
            float4 q1 = *(const float4*)&qs[1][d4 * 4];
            float4 q2 = *(const float4*)&qs[2][d4 * 4];
            float4 q3 = *(const float4*)&qs[3][d4 * 4];
            sc0 += q0.x * k.x + q0.y * k.y + q0.z * k.z + q0.w * k.w;
            sc1 += q1.x * k.x + q1.y * k.y + q1.z * k.z + q1.w * k.w;
            sc2 += q2.x * k.x + q2.y * k.y + q2.z * k.z + q2.w * k.w;
            sc3 += q3.x * k.x + q3.y * k.y + q3.z * k.z + q3.w * k.w;
        }
        float e0 = __expf(sc0), e1 = __expf(sc1), e2 = __expf(sc2), e3 = __expf(sc3);
        dent[0] += e0; dent[1] += e1; dent[2] += e2; dent[3] += e3;
        Es[0][t] = e0; Es[1][t] = e1; Es[2][t] = e2; Es[3][t] = e3;
        __syncthreads();
        // ---- Phase B: coalesced V accumulation (thread = dim) ----
        const float* Vp = cV + baseK + (size_t)t0 * SROW + t;
#pragma unroll 4
        for (int sl = 0; sl < 128; sl += 4) {
            float4 f0 = *(const float4*)&Es[0][sl];
            float4 f1 = *(const float4*)&Es[1][sl];
            float4 f2 = *(const float4*)&Es[2][sl];
            float4 f3 = *(const float4*)&Es[3][sl];
            float v0 = Vp[(size_t)(sl + 0) * SROW];
            float v1 = Vp[(size_t)(sl + 1) * SROW];
            float v2 = Vp[(size_t)(sl + 2) * SROW];
            float v3 = Vp[(size_t)(sl + 3) * SROW];
            O[0] += f0.x * v0 + f0.y * v1 + f0.z * v2 + f0.w * v3;
            O[1] += f1.x * v0 + f1.y * v1 + f1.z * v2 + f1.w * v3;
            O[2] += f2.x * v0 + f2.y * v1 + f2.z * v2 + f2.w * v3;
            O[3] += f3.x * v0 + f3.y * v1 + f3.z * v2 + f3.w * v3;
        }
        __syncthreads();
    }

    // Appended row s = P (k_new/v_new) lives in the last chunk
    if (c == NCHUNK - 1) {
        if (t == 0) {
            const float* kn = g_qkv + (size_t)b * ROWS_TOT + NN + kvh * DD;
#pragma unroll
            for (int g = 0; g < GG; g++) {
                float s0 = 0.f, s1 = 0.f, s2 = 0.f, s3 = 0.f;
                for (int d = 0; d < DD; d += 4) {
                    s0 += qs[g][d + 0] * kn[d + 0];
                    s1 += qs[g][d + 1] * kn[d + 1];
                    s2 += qs[g][d + 2] * kn[d + 2];
                    s3 += qs[g][d + 3] * kn[d + 3];
                }
                float e = __expf(s0 + s1 + s2 + s3);
                Es[g][0] = e;
                dent[g] += e;
            }
        }
        __syncthreads();
        float v = g_qkv[(size_t)b * ROWS_TOT + NN + KNN + kvh * DD + t];
#pragma unroll
        for (int g = 0; g < GG; g++) O[g] += Es[g][0] * v;
    }

    // Reduce per-thread denominators; write partials
#pragma unroll
    for (int g = 0; g < GG; g++) sred[g][t] = dent[g];
    __syncthreads();
    int pb = ((b * KVHH) + kvh) * NCHUNK + c;
    if (t < GG) {
        float s = 0.f;
        for (int i = 0; i < 128; i++) s += sred[t][i];
        g_pden[pb][t] = s;
    }
#pragma unroll
    for (int g = 0; g < GG; g++) g_pnum[pb][g * DD + t] = O[g];
}

// ---------------------------------------------------------------------------
// 4) Epilogue: sum chunk partials, divide, write output [B, N]
// ---------------------------------------------------------------------------
__global__ void attn_epilogue(float* __restrict__ out) {
    int bk = blockIdx.x;   // b*KVHH + kvh
    int t  = threadIdx.x;  // 128
    int b = bk / KVHH, kvh = bk % KVHH;
#pragma unroll
    for (int g = 0; g < GG; g++) {
        float num = 0.f, den = 0.f;
#pragma unroll
        for (int c = 0; c < NCHUNK; c++) {
            int pb = bk * NCHUNK + c;
            num += g_pnum[pb][g * DD + t];
            den += g_pden[pb][g];
        }
        out[(size_t)b * NN + (kvh * GG + g) * DD + t] = num / den;
    }
}

// ---------------------------------------------------------------------------
extern "C" void kernel_launch(void* const* d_in, const int* in_sizes, int n_in,
                              void* d_out, int out_size) {
    const float* X  = (const float*)d_in[0];
    const float* Wq = (const float*)d_in[1];
    const float* Wk = (const float*)d_in[2];
    const float* Wv = (const float*)d_in[3];
    const float* cK = (const float*)d_in[4];
    const float* cV = (const float*)d_in[5];
    float* out = (float*)d_out;

    rms_kernel<<<BB, 256>>>(X);
    qkv_kernel<<<dim3(ROWS_TOT / 128, KSPLIT), 256>>>(Wq, Wk, Wv);
    qkv_reduce<<<(BB * ROWS_TOT) / 256, 256>>>();
    attn_kernel<<<dim3(NCHUNK, KVHH, BB), 128>>>(cK, cV);
    attn_epilogue<<<BB * KVHH, 128>>>(out);
}

// round 7
// speedup vs baseline: 1.4999x; 1.4999x over previous
#include <cuda_runtime.h>

// Problem constants
#define BB   32
#define QHH  32
#define KVHH 8
#define DD   128
#define PP   4096
#define NN   4096       // QHH*DD
#define KNN  1024       // KVHH*DD
#define GG   4          // QHH/KVHH
#define ROWS_TOT 6144   // NN + 2*KNN
#define KSPLIT 8
#define NCHUNK 8
#define CHUNK_S (PP / NCHUNK)   // 512 rows per chunk
#define SROW (KVHH*DD)          // 1024 floats stride over s in cache

// Scratch (device globals; no allocations allowed)
__device__ float g_xnorm[BB * NN];                       // 512 KB
__device__ float g_gpart[KSPLIT][BB * ROWS_TOT];        // 6 MB
__device__ float g_qkv[BB * ROWS_TOT];                  // 768 KB
__device__ float g_pnum[BB * KVHH * NCHUNK][GG * DD];   // 4 MB
__device__ float g_pden[BB * KVHH * NCHUNK][GG];        // 32 KB

// ---------------------------------------------------------------------------
// 1) RMSNorm
// ---------------------------------------------------------------------------
__global__ void rms_kernel(const float* __restrict__ X) {
    int b = blockIdx.x;
    int t = threadIdx.x;  // 256
    const float4* x4 = (const float4*)(X + (size_t)b * NN);
    float ss = 0.f;
    for (int i = t; i < NN / 4; i += 256) {
        float4 a = x4[i];
        ss += a.x * a.x + a.y * a.y + a.z * a.z + a.w * a.w;
    }
    __shared__ float red[256];
    red[t] = ss;
    __syncthreads();
    for (int o = 128; o > 0; o >>= 1) {
        if (t < o) red[t] += red[t + o];
        __syncthreads();
    }
    float scale = rsqrtf(red[0] / (float)NN);
    float4* o4 = (float4*)(g_xnorm + (size_t)b * NN);
    for (int i = t; i < NN / 4; i += 256) {
        float4 a = x4[i];
        a.x *= scale; a.y *= scale; a.z *= scale; a.w *= scale;
        o4[i] = a;
    }
}

// ---------------------------------------------------------------------------
// 2) QKV projection (K-split GEMM, deterministic reduce)
// ---------------------------------------------------------------------------
#define TKC 64
__global__ void qkv_kernel(const float* __restrict__ Wq,
                           const float* __restrict__ Wk,
                           const float* __restrict__ Wv) {
    int rtile = blockIdx.x;   // 0..47
    int ks    = blockIdx.y;   // 0..7
    int tid   = threadIdx.x;  // 256
    int r0 = rtile * 128;
    const float* Wbase;
    if (r0 < NN)            Wbase = Wq + (size_t)r0 * NN;
    else if (r0 < NN + KNN) Wbase = Wk + (size_t)(r0 - NN) * NN;
    else                    Wbase = Wv + (size_t)(r0 - NN - KNN) * NN;
    int k0 = ks * (NN / KSPLIT);  // 512-wide K slice

    __shared__ __align__(16) float xs[BB][TKC];
    __shared__ float ws[128][TKC + 1];

    int rq = tid & 31;
    int bq = tid >> 5;

    float acc[4][4];
#pragma unroll
    for (int i = 0; i < 4; i++)
#pragma unroll
        for (int j = 0; j < 4; j++) acc[i][j] = 0.f;

    for (int kc = 0; kc < NN / KSPLIT; kc += TKC) {
        for (int idx = tid; idx < BB * (TKC / 4); idx += 256) {
            int bb = idx / (TKC / 4), c4 = idx % (TKC / 4);
            float4 v = *(const float4*)(g_xnorm + (size_t)bb * NN + k0 + kc + c4 * 4);
            *(float4*)&xs[bb][c4 * 4] = v;
        }
        for (int idx = tid; idx < 128 * (TKC / 4); idx += 256) {
            int r = idx / (TKC / 4), c4 = idx % (TKC / 4);
            float4 v = *(const float4*)(Wbase + (size_t)r * NN + k0 + kc + c4 * 4);
            ws[r][c4 * 4 + 0] = v.x;
            ws[r][c4 * 4 + 1] = v.y;
            ws[r][c4 * 4 + 2] = v.z;
            ws[r][c4 * 4 + 3] = v.w;
        }
        __syncthreads();
#pragma unroll 8
        for (int k = 0; k < TKC; k++) {
            float xv[4], wv[4];
#pragma unroll
            for (int i = 0; i < 4; i++) xv[i] = xs[bq * 4 + i][k];
#pragma unroll
            for (int j = 0; j < 4; j++) wv[j] = ws[rq + 32 * j][k];
#pragma unroll
            for (int i = 0; i < 4; i++)
#pragma unroll
                for (int j = 0; j < 4; j++) acc[i][j] += xv[i] * wv[j];
        }
        __syncthreads();
    }
#pragma unroll
    for (int i = 0; i < 4; i++) {
        int bb = bq * 4 + i;
#pragma unroll
        for (int j = 0; j < 4; j++) {
            int r = r0 + rq + 32 * j;
            g_gpart[ks][(size_t)bb * ROWS_TOT + r] = acc[i][j];
        }
    }
}

__global__ void qkv_reduce() {
    int idx = blockIdx.x * 256 + threadIdx.x;
    float s = 0.f;
#pragma unroll
    for (int ks = 0; ks < KSPLIT; ks++) s += g_gpart[ks][idx];
    g_qkv[idx] = s;
}

// ---------------------------------------------------------------------------
// 3) Split-KV attention (non-stabilized softmax is linear over S-partitions).
//    Phase A: thread = KV row; K rows streamed as 8-deep float4 batches (MLP).
//    Phase B: thread = (dim-float4, row-subgroup); V streamed as float4,
//    e-values broadcast via one LDS.128 per row.
//    __launch_bounds__(128,4) -> <=128 regs -> 4 CTAs/SM.
// ---------------------------------------------------------------------------
__global__ void __launch_bounds__(128, 4)
attn_kernel(const float* __restrict__ cK, const float* __restrict__ cV) {
    int c   = blockIdx.x;   // chunk 0..NCHUNK-1
    int kvh = blockIdx.y;   // 0..7
    int b   = blockIdx.z;   // 0..31
    int t   = threadIdx.x;  // 128
    int c4  = t & 31;       // dim float4 index (phase B)
    int rg  = t >> 5;       // row subgroup 0..3  (== warp id)

    __shared__ __align__(16) float qs[GG][DD];        // 2 KB
    __shared__ __align__(16) float4 Es4[128];         // 2 KB
    __shared__ float redO[4][GG][DD];                 // 8 KB
    __shared__ float sred[GG][128];                   // 2 KB

    for (int i = t; i < GG * DD; i += 128) {
        int g = i >> 7, d = i & 127;
        qs[g][d] = g_qkv[(size_t)b * ROWS_TOT + (kvh * GG + g) * DD + d];
    }
    __syncthreads();

    float4 O0 = {0,0,0,0}, O1 = {0,0,0,0}, O2 = {0,0,0,0}, O3 = {0,0,0,0};
    float dent0 = 0.f, dent1 = 0.f, dent2 = 0.f, dent3 = 0.f;
    const size_t baseK = ((size_t)b * PP) * SROW + (size_t)kvh * DD;

    for (int t0 = c * CHUNK_S; t0 < c * CHUNK_S + CHUNK_S; t0 += 128) {
        // ---- Phase A: scores + exp, one KV row per thread ----
        int s = t0 + t;
        const float4* K4 = (const float4*)(cK + baseK + (size_t)s * SROW);
        float sc0 = 0.f, sc1 = 0.f, sc2 = 0.f, sc3 = 0.f;
        float4 kv[8];
#pragma unroll
        for (int h = 0; h < 4; h++) {
#pragma unroll
            for (int u = 0; u < 8; u++) kv[u] = K4[h * 8 + u];
#pragma unroll
            for (int u = 0; u < 8; u++) {
                int d4 = h * 8 + u;
                float4 k  = kv[u];
                float4 q0 = *(const float4*)&qs[0][d4 * 4];
                float4 q1 = *(const float4*)&qs[1][d4 * 4];
                float4 q2 = *(const float4*)&qs[2][d4 * 4];
                float4 q3 = *(const float4*)&qs[3][d4 * 4];
                sc0 += q0.x * k.x + q0.y * k.y + q0.z * k.z + q0.w * k.w;
                sc1 += q1.x * k.x + q1.y * k.y + q1.z * k.z + q1.w * k.w;
                sc2 += q2.x * k.x + q2.y * k.y + q2.z * k.z + q2.w * k.w;
                sc3 += q3.x * k.x + q3.y * k.y + q3.z * k.z + q3.w * k.w;
            }
        }
        float4 e;
        e.x = __expf(sc0); e.y = __expf(sc1); e.z = __expf(sc2); e.w = __expf(sc3);
        dent0 += e.x; dent1 += e.y; dent2 += e.z; dent3 += e.w;
        Es4[t] = e;
        __syncthreads();

        // ---- Phase B: V accumulation, float4 over dims, rows rg+4j ----
        const float4* V4 = (const float4*)(cV + baseK + (size_t)(t0 + rg) * SROW) + c4;
#pragma unroll 8
        for (int j = 0; j < 32; j++) {
            float4 v = V4[(size_t)j * SROW];       // +4 rows per j
            float4 f = Es4[rg + 4 * j];            // warp-uniform broadcast
            O0.x += f.x * v.x; O0.y += f.x * v.y; O0.z += f.x * v.z; O0.w += f.x * v.w;
            O1.x += f.y * v.x; O1.y += f.y * v.y; O1.z += f.y * v.z; O1.w += f.y * v.w;
            O2.x += f.z * v.x; O2.y += f.z * v.y; O2.z += f.z * v.z; O2.w += f.z * v.w;
            O3.x += f.w * v.x; O3.y += f.w * v.y; O3.z += f.w * v.z; O3.w += f.w * v.w;
        }
        __syncthreads();
    }

    // Appended row s = P (k_new/v_new): last chunk only
    if (c == NCHUNK - 1) {
        if (t == 0) {
            const float* kn = g_qkv + (size_t)b * ROWS_TOT + NN + kvh * DD;
            float4 e;
            float* ep = &e.x;
#pragma unroll
            for (int g = 0; g < GG; g++) {
                float s0 = 0.f, s1 = 0.f, s2 = 0.f, s3 = 0.f;
                for (int d = 0; d < DD; d += 4) {
                    s0 += qs[g][d + 0] * kn[d + 0];
                    s1 += qs[g][d + 1] * kn[d + 1];
                    s2 += qs[g][d + 2] * kn[d + 2];
                    s3 += qs[g][d + 3] * kn[d + 3];
                }
                ep[g] = __expf(s0 + s1 + s2 + s3);
            }
            Es4[0] = e;
            dent0 += e.x; dent1 += e.y; dent2 += e.z; dent3 += e.w;
        }
        __syncthreads();
        if (rg == 0) {  // exactly one subgroup adds the appended row
            float4 v = *(const float4*)(g_qkv + (size_t)b * ROWS_TOT + NN + KNN
                                        + kvh * DD + c4 * 4);
            float4 f = Es4[0];
            O0.x += f.x * v.x; O0.y += f.x * v.y; O0.z += f.x * v.z; O0.w += f.x * v.w;
            O1.x += f.y * v.x; O1.y += f.y * v.y; O1.z += f.y * v.z; O1.w += f.y * v.w;
            O2.x += f.z * v.x; O2.y += f.z * v.y; O2.z += f.z * v.z; O2.w += f.z * v.w;
            O3.x += f.w * v.x; O3.y += f.w * v.y; O3.z += f.w * v.z; O3.w += f.w * v.w;
        }
        __syncthreads();
    }

    // Reduce O across the 4 row-subgroups, and denominators across threads
    int d0 = c4 * 4;
    redO[rg][0][d0+0] = O0.x; redO[rg][0][d0+1] = O0.y; redO[rg][0][d0+2] = O0.z; redO[rg][0][d0+3] = O0.w;
    redO[rg][1][d0+0] = O1.x; redO[rg][1][d0+1] = O1.y; redO[rg][1][d0+2] = O1.z; redO[rg][1][d0+3] = O1.w;
    redO[rg][2][d0+0] = O2.x; redO[rg][2][d0+1] = O2.y; redO[rg][2][d0+2] = O2.z; redO[rg][2][d0+3] = O2.w;
    redO[rg][3][d0+0] = O3.x; redO[rg][3][d0+1] = O3.y; redO[rg][3][d0+2] = O3.z; redO[rg][3][d0+3] = O3.w;
    sred[0][t] = dent0; sred[1][t] = dent1; sred[2][t] = dent2; sred[3][t] = dent3;
    __syncthreads();

    int pb = ((b * KVHH) + kvh) * NCHUNK + c;
    if (t < GG) {
        float s = 0.f;
        for (int i = 0; i < 128; i++) s += sred[t][i];
        g_pden[pb][t] = s;
    }
#pragma unroll
    for (int g = 0; g < GG; g++) {
        float num = redO[0][g][t] + redO[1][g][t] + redO[2][g][t] + redO[3][g][t];
        g_pnum[pb][g * DD + t] = num;
    }
}

// ---------------------------------------------------------------------------
// 4) Epilogue: sum chunk partials, divide, write [B, N]
// ---------------------------------------------------------------------------
__global__ void attn_epilogue(float* __restrict__ out) {
    int bk = blockIdx.x;   // b*KVHH + kvh
    int t  = threadIdx.x;  // 128
    int b = bk / KVHH, kvh = bk % KVHH;
#pragma unroll
    for (int g = 0; g < GG; g++) {
        float num = 0.f, den = 0.f;
#pragma unroll
        for (int c = 0; c < NCHUNK; c++) {
            int pb = bk * NCHUNK + c;
            num += g_pnum[pb][g * DD + t];
            den += g_pden[pb][g];
        }
        out[(size_t)b * NN + (kvh * GG + g) * DD + t] = num / den;
    }
}

// ---------------------------------------------------------------------------
extern "C" void kernel_launch(void* const* d_in, const int* in_sizes, int n_in,
                              void* d_out, int out_size) {
    const float* X  = (const float*)d_in[0];
    const float* Wq = (const float*)d_in[1];
    const float* Wk = (const float*)d_in[2];
    const float* Wv = (const float*)d_in[3];
    const float* cK = (const float*)d_in[4];
    const float* cV = (const float*)d_in[5];
    float* out = (float*)d_out;

    rms_kernel<<<BB, 256>>>(X);
    qkv_kernel<<<dim3(ROWS_TOT / 128, KSPLIT), 256>>>(Wq, Wk, Wv);
    qkv_reduce<<<(BB * ROWS_TOT) / 256, 256>>>();
    attn_kernel<<<dim3(NCHUNK, KVHH, BB), 128>>>(cK, cV);
    attn_epilogue<<<BB * KVHH, 128>>>(out);
}

// round 8
// speedup vs baseline: 1.6964x; 1.1310x over previous
#include <cuda_runtime.h>

// Problem constants
#define BB   32
#define QHH  32
#define KVHH 8
#define DD   128
#define PP   4096
#define NN   4096       // QHH*DD
#define KNN  1024       // KVHH*DD
#define GG   4          // QHH/KVHH
#define ROWS_TOT 6144   // NN + 2*KNN
#define KSPLIT 8
#define NCHUNK 8
#define CHUNK_S (PP / NCHUNK)   // 512 rows per chunk
#define SROW (KVHH*DD)          // 1024 floats stride over s in cache

// Scratch (device globals; no allocations allowed)
__device__ float g_xnorm[BB * NN];
__device__ float g_gpart[KSPLIT][BB * ROWS_TOT];
__device__ float g_qkv[BB * ROWS_TOT];
__device__ float g_pnum[BB * KVHH * NCHUNK][GG * DD];
__device__ float g_pden[BB * KVHH * NCHUNK][GG];

// ---------------------------------------------------------------------------
// 1) RMSNorm
// ---------------------------------------------------------------------------
__global__ void rms_kernel(const float* __restrict__ X) {
    int b = blockIdx.x;
    int t = threadIdx.x;  // 256
    const float4* x4 = (const float4*)(X + (size_t)b * NN);
    float ss = 0.f;
    for (int i = t; i < NN / 4; i += 256) {
        float4 a = x4[i];
        ss += a.x * a.x + a.y * a.y + a.z * a.z + a.w * a.w;
    }
    __shared__ float red[256];
    red[t] = ss;
    __syncthreads();
    for (int o = 128; o > 0; o >>= 1) {
        if (t < o) red[t] += red[t + o];
        __syncthreads();
    }
    float scale = rsqrtf(red[0] / (float)NN);
    float4* o4 = (float4*)(g_xnorm + (size_t)b * NN);
    for (int i = t; i < NN / 4; i += 256) {
        float4 a = x4[i];
        a.x *= scale; a.y *= scale; a.z *= scale; a.w *= scale;
        o4[i] = a;
    }
}

// ---------------------------------------------------------------------------
// 2) QKV projection (K-split GEMM). Vectorized LDS.128 operand reads:
//    pad-68 rows -> conflict-free float4 smem loads; 8 LDS + 64 FMA / 4 k.
// ---------------------------------------------------------------------------
#define TKC 64
__global__ void qkv_kernel(const float* __restrict__ Wq,
                           const float* __restrict__ Wk,
                           const float* __restrict__ Wv) {
    int rtile = blockIdx.x;   // 0..47
    int ks    = blockIdx.y;   // 0..7
    int tid   = threadIdx.x;  // 256
    int r0 = rtile * 128;
    const float* Wbase;
    if (r0 < NN)            Wbase = Wq + (size_t)r0 * NN;
    else if (r0 < NN + KNN) Wbase = Wk + (size_t)(r0 - NN) * NN;
    else                    Wbase = Wv + (size_t)(r0 - NN - KNN) * NN;
    int k0 = ks * (NN / KSPLIT);  // 512-wide K slice

    __shared__ __align__(16) float xs[BB][TKC + 4];    // pad 68
    __shared__ __align__(16) float ws[128][TKC + 4];   // pad 68

    int rq = tid & 31;
    int bq = tid >> 5;

    float acc[4][4];
#pragma unroll
    for (int i = 0; i < 4; i++)
#pragma unroll
        for (int j = 0; j < 4; j++) acc[i][j] = 0.f;

    for (int kc = 0; kc < NN / KSPLIT; kc += TKC) {
        // x tile: 32 rows x 64 floats (512 float4, 2 per thread)
#pragma unroll
        for (int i = 0; i < 2; i++) {
            int idx = tid + 256 * i;
            int bb = idx >> 4, c = idx & 15;
            float4 v = *(const float4*)(g_xnorm + (size_t)bb * NN + k0 + kc + c * 4);
            *(float4*)&xs[bb][c * 4] = v;
        }
        // W tile: 128 rows x 64 floats (2048 float4, 8 per thread)
#pragma unroll
        for (int i = 0; i < 8; i++) {
            int idx = tid + 256 * i;
            int r = idx >> 4, c = idx & 15;
            float4 v = *(const float4*)(Wbase + (size_t)r * NN + k0 + kc + c * 4);
            *(float4*)&ws[r][c * 4] = v;
        }
        __syncthreads();
#pragma unroll
        for (int kk = 0; kk < TKC; kk += 4) {
            float4 xv[4], wv[4];
#pragma unroll
            for (int i = 0; i < 4; i++) xv[i] = *(const float4*)&xs[bq * 4 + i][kk];
#pragma unroll
            for (int j = 0; j < 4; j++) wv[j] = *(const float4*)&ws[rq + 32 * j][kk];
#pragma unroll
            for (int i = 0; i < 4; i++)
#pragma unroll
                for (int j = 0; j < 4; j++) {
                    acc[i][j] += xv[i].x * wv[j].x;
                    acc[i][j] += xv[i].y * wv[j].y;
                    acc[i][j] += xv[i].z * wv[j].z;
                    acc[i][j] += xv[i].w * wv[j].w;
                }
        }
        __syncthreads();
    }
#pragma unroll
    for (int i = 0; i < 4; i++) {
        int bb = bq * 4 + i;
#pragma unroll
        for (int j = 0; j < 4; j++) {
            int r = r0 + rq + 32 * j;
            g_gpart[ks][(size_t)bb * ROWS_TOT + r] = acc[i][j];
        }
    }
}

__global__ void qkv_reduce() {
    int idx = blockIdx.x * 256 + threadIdx.x;
    float s = 0.f;
#pragma unroll
    for (int ks = 0; ks < KSPLIT; ks++) s += g_gpart[ks][idx];
    g_qkv[idx] = s;
}

// ---------------------------------------------------------------------------
// 3) Split-KV attention (non-stabilized softmax is linear over S-partitions).
//    Phase A: K staged through smem — cooperative COALESCED load of a
//    128-row x 64-dim half-tile (pad 68 -> conflict-free LDS.128), then
//    thread = row reads from smem. Kills the 32-wavefront/instr LDG pattern.
//    Phase B: thread = (dim-float4, row-subgroup); coalesced float4 V reads,
//    e broadcast via one LDS.128 per row.
// ---------------------------------------------------------------------------
__global__ void __launch_bounds__(128, 4)
attn_kernel(const float* __restrict__ cK, const float* __restrict__ cV) {
    int c   = blockIdx.x;   // chunk
    int kvh = blockIdx.y;   // 0..7
    int b   = blockIdx.z;   // 0..31
    int t   = threadIdx.x;  // 128
    int c4  = t & 31;       // dim float4 index (phase B)
    int rg  = t >> 5;       // row subgroup / warp id
    int lane = t & 31;

    __shared__ __align__(16) float ks[128][68];       // 34816 B
    __shared__ __align__(16) float qs[GG][DD];        // 2048 B
    __shared__ __align__(16) float4 Es4[128];         // 2048 B
    __shared__ float redO[4][GG][DD];                 // 8192 B
    __shared__ float sredW[4][GG];                    // 64 B

    for (int i = t; i < GG * DD; i += 128) {
        int g = i >> 7, d = i & 127;
        qs[g][d] = g_qkv[(size_t)b * ROWS_TOT + (kvh * GG + g) * DD + d];
    }
    __syncthreads();

    float4 O0 = {0,0,0,0}, O1 = {0,0,0,0}, O2 = {0,0,0,0}, O3 = {0,0,0,0};
    float dent0 = 0.f, dent1 = 0.f, dent2 = 0.f, dent3 = 0.f;
    const size_t baseK = ((size_t)b * PP) * SROW + (size_t)kvh * DD;

    for (int t0 = c * CHUNK_S; t0 < c * CHUNK_S + CHUNK_S; t0 += 128) {
        // ---- Phase A: scores via smem-staged K ----
        float sc0 = 0.f, sc1 = 0.f, sc2 = 0.f, sc3 = 0.f;
#pragma unroll
        for (int dh = 0; dh < 2; dh++) {
            // coalesced load: 128 rows x 64 floats = 2048 float4, 16/thread
#pragma unroll
            for (int i = 0; i < 16; i++) {
                int idx = i * 128 + t;
                int r = idx >> 4, cc = idx & 15;
                float4 v = *(const float4*)(cK + baseK + (size_t)(t0 + r) * SROW
                                            + dh * 64 + cc * 4);
                *(float4*)&ks[r][cc * 4] = v;
            }
            __syncthreads();
#pragma unroll
            for (int d4 = 0; d4 < 16; d4++) {
                float4 k  = *(const float4*)&ks[t][d4 * 4];
                int dq = dh * 64 + d4 * 4;
                float4 q0 = *(const float4*)&qs[0][dq];
                float4 q1 = *(const float4*)&qs[1][dq];
                float4 q2 = *(const float4*)&qs[2][dq];
                float4 q3 = *(const float4*)&qs[3][dq];
                sc0 += q0.x * k.x + q0.y * k.y + q0.z * k.z + q0.w * k.w;
                sc1 += q1.x * k.x + q1.y * k.y + q1.z * k.z + q1.w * k.w;
                sc2 += q2.x * k.x + q2.y * k.y + q2.z * k.z + q2.w * k.w;
                sc3 += q3.x * k.x + q3.y * k.y + q3.z * k.z + q3.w * k.w;
            }
            __syncthreads();
        }
        float4 e;
        e.x = __expf(sc0); e.y = __expf(sc1); e.z = __expf(sc2); e.w = __expf(sc3);
        dent0 += e.x; dent1 += e.y; dent2 += e.z; dent3 += e.w;
        Es4[t] = e;
        __syncthreads();

        // ---- Phase B: V accumulation, float4 over dims, rows rg+4j ----
        const float4* V4 = (const float4*)(cV + baseK + (size_t)(t0 + rg) * SROW) + c4;
#pragma unroll 8
        for (int j = 0; j < 32; j++) {
            float4 v = V4[(size_t)j * SROW];       // +4 rows per j
            float4 f = Es4[rg + 4 * j];            // warp-uniform broadcast
            O0.x += f.x * v.x; O0.y += f.x * v.y; O0.z += f.x * v.z; O0.w += f.x * v.w;
            O1.x += f.y * v.x; O1.y += f.y * v.y; O1.z += f.y * v.z; O1.w += f.y * v.w;
            O2.x += f.z * v.x; O2.y += f.z * v.y; O2.z += f.z * v.z; O2.w += f.z * v.w;
            O3.x += f.w * v.x; O3.y += f.w * v.y; O3.z += f.w * v.z; O3.w += f.w * v.w;
        }
        __syncthreads();
    }

    // Appended row s = P (k_new/v_new): last chunk only
    if (c == NCHUNK - 1) {
        if (t == 0) {
            const float* kn = g_qkv + (size_t)b * ROWS_TOT + NN + kvh * DD;
            float4 e;
            float* ep = &e.x;
#pragma unroll
            for (int g = 0; g < GG; g++) {
                float s0 = 0.f, s1 = 0.f, s2 = 0.f, s3 = 0.f;
                for (int d = 0; d < DD; d += 4) {
                    s0 += qs[g][d + 0] * kn[d + 0];
                    s1 += qs[g][d + 1] * kn[d + 1];
                    s2 += qs[g][d + 2] * kn[d + 2];
                    s3 += qs[g][d + 3] * kn[d + 3];
                }
                ep[g] = __expf(s0 + s1 + s2 + s3);
            }
            Es4[0] = e;
            dent0 += e.x; dent1 += e.y; dent2 += e.z; dent3 += e.w;
        }
        __syncthreads();
        if (rg == 0) {  // exactly one subgroup adds the appended row
            float4 v = *(const float4*)(g_qkv + (size_t)b * ROWS_TOT + NN + KNN
                                        + kvh * DD + c4 * 4);
            float4 f = Es4[0];
            O0.x += f.x * v.x; O0.y += f.x * v.y; O0.z += f.x * v.z; O0.w += f.x * v.w;
            O1.x += f.y * v.x; O1.y += f.y * v.y; O1.z += f.y * v.z; O1.w += f.y * v.w;
            O2.x += f.z * v.x; O2.y += f.z * v.y; O2.z += f.z * v.z; O2.w += f.z * v.w;
            O3.x += f.w * v.x; O3.y += f.w * v.y; O3.z += f.w * v.z; O3.w += f.w * v.w;
        }
        __syncthreads();
    }

    // Denominators: shfl-reduce within warp, then tiny smem combine
    for (int o = 16; o > 0; o >>= 1) {
        dent0 += __shfl_xor_sync(0xffffffffu, dent0, o);
        dent1 += __shfl_xor_sync(0xffffffffu, dent1, o);
        dent2 += __shfl_xor_sync(0xffffffffu, dent2, o);
        dent3 += __shfl_xor_sync(0xffffffffu, dent3, o);
    }
    if (lane == 0) {
        sredW[rg][0] = dent0; sredW[rg][1] = dent1;
        sredW[rg][2] = dent2; sredW[rg][3] = dent3;
    }
    // O partials across the 4 row-subgroups
    int d0 = c4 * 4;
    redO[rg][0][d0+0] = O0.x; redO[rg][0][d0+1] = O0.y; redO[rg][0][d0+2] = O0.z; redO[rg][0][d0+3] = O0.w;
    redO[rg][1][d0+0] = O1.x; redO[rg][1][d0+1] = O1.y; redO[rg][1][d0+2] = O1.z; redO[rg][1][d0+3] = O1.w;
    redO[rg][2][d0+0] = O2.x; redO[rg][2][d0+1] = O2.y; redO[rg][2][d0+2] = O2.z; redO[rg][2][d0+3] = O2.w;
    redO[rg][3][d0+0] = O3.x; redO[rg][3][d0+1] = O3.y; redO[rg][3][d0+2] = O3.z; redO[rg][3][d0+3] = O3.w;
    __syncthreads();

    int pb = ((b * KVHH) + kvh) * NCHUNK + c;
    if (t < GG) {
        g_pden[pb][t] = sredW[0][t] + sredW[1][t] + sredW[2][t] + sredW[3][t];
    }
#pragma unroll
    for (int g = 0; g < GG; g++) {
        float num = redO[0][g][t] + redO[1][g][t] + redO[2][g][t] + redO[3][g][t];
        g_pnum[pb][g * DD + t] = num;
    }
}

// ---------------------------------------------------------------------------
// 4) Epilogue: sum chunk partials, divide, write [B, N]
// ---------------------------------------------------------------------------
__global__ void attn_epilogue(float* __restrict__ out) {
    int bk = blockIdx.x;   // b*KVHH + kvh
    int t  = threadIdx.x;  // 128
    int b = bk / KVHH, kvh = bk % KVHH;
#pragma unroll
    for (int g = 0; g < GG; g++) {
        float num = 0.f, den = 0.f;
#pragma unroll
        for (int c = 0; c < NCHUNK; c++) {
            int pb = bk * NCHUNK + c;
            num += g_pnum[pb][g * DD + t];
            den += g_pden[pb][g];
        }
        out[(size_t)b * NN + (kvh * GG + g) * DD + t] = num / den;
    }
}

// ---------------------------------------------------------------------------
extern "C" void kernel_launch(void* const* d_in, const int* in_sizes, int n_in,
                              void* d_out, int out_size) {
    const float* X  = (const float*)d_in[0];
    const float* Wq = (const float*)d_in[1];
    const float* Wk = (const float*)d_in[2];
    const float* Wv = (const float*)d_in[3];
    const float* cK = (const float*)d_in[4];
    const float* cV = (const float*)d_in[5];
    float* out = (float*)d_out;

    rms_kernel<<<BB, 256>>>(X);
    qkv_kernel<<<dim3(ROWS_TOT / 128, KSPLIT), 256>>>(Wq, Wk, Wv);
    qkv_reduce<<<(BB * ROWS_TOT) / 256, 256>>>();
    attn_kernel<<<dim3(NCHUNK, KVHH, BB), 128>>>(cK, cV);
    attn_epilogue<<<BB * KVHH, 128>>>(out);
}

// round 11
// speedup vs baseline: 1.8692x; 1.1019x over previous
#include <cuda_runtime.h>

// Problem constants
#define BB   32
#define QHH  32
#define KVHH 8
#define DD   128
#define PP   4096
#define NN   4096       // QHH*DD
#define KNN  1024       // KVHH*DD
#define GG   4          // QHH/KVHH
#define ROWS_TOT 6144   // NN + 2*KNN
#define KSPLIT 8
#define NCHUNK 8
#define CHUNK_S (PP / NCHUNK)   // 512 rows per chunk
#define SROW (KVHH*DD)          // 1024 floats stride over s in cache
#define QW   32                 // K staging quarter width (dims)
#define KPAD 36                 // padded row width for staging buffers

// Scratch (device globals; no allocations allowed)
__device__ float g_xnorm[BB * NN];
__device__ float g_gpart[KSPLIT][BB * ROWS_TOT];
__device__ float g_qkv[BB * ROWS_TOT];
__device__ float g_pnum[BB * KVHH * NCHUNK][GG * DD];
__device__ float g_pden[BB * KVHH * NCHUNK][GG];

// ---- helpers: packed f32x2 FMA, cp.async ----------------------------------
__device__ __forceinline__ void fma2(unsigned long long& d,
                                     unsigned long long a,
                                     unsigned long long b) {
    asm("fma.rn.f32x2 %0, %1, %2, %3;" : "=l"(d) : "l"(a), "l"(b), "l"(d));
}
__device__ __forceinline__ unsigned long long pack2(float x, float y) {
    unsigned long long r;
    asm("mov.b64 %0, {%1, %2};" : "=l"(r) : "f"(x), "f"(y));
    return r;
}
__device__ __forceinline__ float2 unpack2(unsigned long long v) {
    float2 r;
    asm("mov.b64 {%0, %1}, %2;" : "=f"(r.x), "=f"(r.y) : "l"(v));
    return r;
}
__device__ __forceinline__ void cp_async16(void* smem_dst, const void* gsrc) {
    unsigned s = (unsigned)__cvta_generic_to_shared(smem_dst);
    asm volatile("cp.async.cg.shared.global [%0], [%1], 16;\n" :: "r"(s), "l"(gsrc));
}
#define CP_COMMIT() asm volatile("cp.async.commit_group;\n" ::: "memory")
#define CP_WAIT1()  asm volatile("cp.async.wait_group 1;\n" ::: "memory")
#define CP_WAIT0()  asm volatile("cp.async.wait_group 0;\n" ::: "memory")

// ---------------------------------------------------------------------------
// 1) RMSNorm
// ---------------------------------------------------------------------------
__global__ void rms_kernel(const float* __restrict__ X) {
    int b = blockIdx.x;
    int t = threadIdx.x;  // 256
    const float4* x4 = (const float4*)(X + (size_t)b * NN);
    float ss = 0.f;
    for (int i = t; i < NN / 4; i += 256) {
        float4 a = x4[i];
        ss += a.x * a.x + a.y * a.y + a.z * a.z + a.w * a.w;
    }
    __shared__ float red[256];
    red[t] = ss;
    __syncthreads();
    for (int o = 128; o > 0; o >>= 1) {
        if (t < o) red[t] += red[t + o];
        __syncthreads();
    }
    float scale = rsqrtf(red[0] / (float)NN);
    float4* o4 = (float4*)(g_xnorm + (size_t)b * NN);
    for (int i = t; i < NN / 4; i += 256) {
        float4 a = x4[i];
        a.x *= scale; a.y *= scale; a.z *= scale; a.w *= scale;
        o4[i] = a;
    }
}

// ---------------------------------------------------------------------------
// 2) QKV projection (K-split GEMM) — packed f32x2 FMA inner loop
// ---------------------------------------------------------------------------
#define TKC 64
__global__ void qkv_kernel(const float* __restrict__ Wq,
                           const float* __restrict__ Wk,
                           const float* __restrict__ Wv) {
    int rtile = blockIdx.x;   // 0..47
    int ks    = blockIdx.y;   // 0..7
    int tid   = threadIdx.x;  // 256
    int r0 = rtile * 128;
    const float* Wbase;
    if (r0 < NN)            Wbase = Wq + (size_t)r0 * NN;
    else if (r0 < NN + KNN) Wbase = Wk + (size_t)(r0 - NN) * NN;
    else                    Wbase = Wv + (size_t)(r0 - NN - KNN) * NN;
    int k0 = ks * (NN / KSPLIT);  // 512-wide K slice

    __shared__ __align__(16) float xs[BB][TKC + 4];    // pad 68
    __shared__ __align__(16) float ws[128][TKC + 4];

    int rq = tid & 31;
    int bq = tid >> 5;

    unsigned long long acc2[4][4];
#pragma unroll
    for (int i = 0; i < 4; i++)
#pragma unroll
        for (int j = 0; j < 4; j++) acc2[i][j] = 0ull;

    for (int kc = 0; kc < NN / KSPLIT; kc += TKC) {
#pragma unroll
        for (int i = 0; i < 2; i++) {
            int idx = tid + 256 * i;
            int bb = idx >> 4, c = idx & 15;
            float4 v = *(const float4*)(g_xnorm + (size_t)bb * NN + k0 + kc + c * 4);
            *(float4*)&xs[bb][c * 4] = v;
        }
#pragma unroll
        for (int i = 0; i < 8; i++) {
            int idx = tid + 256 * i;
            int r = idx >> 4, c = idx & 15;
            float4 v = *(const float4*)(Wbase + (size_t)r * NN + k0 + kc + c * 4);
            *(float4*)&ws[r][c * 4] = v;
        }
        __syncthreads();
#pragma unroll
        for (int kk = 0; kk < TKC; kk += 4) {
            ulonglong2 xv[4], wv[4];
#pragma unroll
            for (int i = 0; i < 4; i++) xv[i] = *(const ulonglong2*)&xs[bq * 4 + i][kk];
#pragma unroll
            for (int j = 0; j < 4; j++) wv[j] = *(const ulonglong2*)&ws[rq + 32 * j][kk];
#pragma unroll
            for (int i = 0; i < 4; i++)
#pragma unroll
                for (int j = 0; j < 4; j++) {
                    fma2(acc2[i][j], xv[i].x, wv[j].x);
                    fma2(acc2[i][j], xv[i].y, wv[j].y);
                }
        }
        __syncthreads();
    }
#pragma unroll
    for (int i = 0; i < 4; i++) {
        int bb = bq * 4 + i;
#pragma unroll
        for (int j = 0; j < 4; j++) {
            int r = r0 + rq + 32 * j;
            float2 p = unpack2(acc2[i][j]);
            g_gpart[ks][(size_t)bb * ROWS_TOT + r] = p.x + p.y;
        }
    }
}

__global__ void qkv_reduce() {
    int idx = blockIdx.x * 256 + threadIdx.x;
    float s = 0.f;
#pragma unroll
    for (int ks = 0; ks < KSPLIT; ks++) s += g_gpart[ks][idx];
    g_qkv[idx] = s;
}

// ---------------------------------------------------------------------------
// 3) Split-KV attention. K staged via double-buffered cp.async in 32-dim
//    quarters (128 rows x 32 floats -> fits the 36-float padded rows).
//    Quarter q+1 is always in flight while quarter q's scores compute; the
//    next tile's quarter 0 streams during the whole V phase.
//    Phase B row stride: 4 rows per j = 4*SROW floats = SROW ulonglong2
//    (16B elements!) — this was the R8-R10 bug.
// ---------------------------------------------------------------------------
__global__ void __launch_bounds__(128, 4)
attn_kernel(const float* __restrict__ cK, const float* __restrict__ cV) {
    int c   = blockIdx.x;   // chunk
    int kvh = blockIdx.y;   // 0..7
    int b   = blockIdx.z;   // 0..31
    int t   = threadIdx.x;  // 128
    int c4  = t & 31;       // dim float4 index (phase B)
    int rg  = t >> 5;       // row subgroup / warp id
    int lane = t & 31;

    __shared__ __align__(16) float ksm[2][128][KPAD]; // 36864 B
    __shared__ __align__(16) float qs[GG][DD];        // 2048 B
    __shared__ __align__(16) float4 Es4[128];         // 2048 B
    __shared__ __align__(16) float redO[4][GG][DD];   // 8192 B => 49152 total
    float* sredW = (float*)&Es4[64];                  // aliased: dead when used

    for (int i = t; i < GG * DD; i += 128) {
        int g = i >> 7, d = i & 127;
        qs[g][d] = g_qkv[(size_t)b * ROWS_TOT + (kvh * GG + g) * DD + d];
    }

    const size_t baseK = ((size_t)b * PP) * SROW + (size_t)kvh * DD;
    // quarter-load geometry: 128 rows x 8 float4; thread covers rows lr+16i
    const int lr = t >> 3, lc = (t & 7) * 4;

    unsigned long long O0a=0,O0b=0,O1a=0,O1b=0,O2a=0,O2b=0,O3a=0,O3b=0;
    float dent0 = 0.f, dent1 = 0.f, dent2 = 0.f, dent3 = 0.f;

    const int s_begin = c * CHUNK_S, s_end = s_begin + CHUNK_S;

    // prologue: issue quarter 0 of first tile into buffer 0
    {
        const float* src = cK + baseK + (size_t)(s_begin + lr) * SROW + lc;
        float* dst = &ksm[0][lr][lc];
#pragma unroll
        for (int i = 0; i < 8; i++)
            cp_async16(dst + i * 16 * KPAD, src + (size_t)i * 16 * SROW);
        CP_COMMIT();
    }

    int buf = 0;  // buffer holding the quarter about to be consumed
    for (int t0 = s_begin; t0 < s_end; t0 += 128) {
        unsigned long long sca0 = 0ull, sca1 = 0ull, sca2 = 0ull, sca3 = 0ull;
#pragma unroll
        for (int q = 0; q < 4; q++) {
            bool last = (t0 + 128 >= s_end) && (q == 3);
            if (!last) {
                int nt0 = (q == 3) ? t0 + 128 : t0;
                int nq  = (q == 3) ? 0 : q + 1;
                const float* src = cK + baseK + (size_t)(nt0 + lr) * SROW
                                   + nq * QW + lc;
                float* dst = &ksm[buf ^ 1][lr][lc];
#pragma unroll
                for (int i = 0; i < 8; i++)
                    cp_async16(dst + i * 16 * KPAD, src + (size_t)i * 16 * SROW);
                CP_COMMIT();
                CP_WAIT1();
            } else {
                CP_WAIT0();
            }
            __syncthreads();
            // scores on quarter q (dims q*32 .. q*32+31) from ksm[buf]
#pragma unroll
            for (int d4 = 0; d4 < 8; d4++) {
                ulonglong2 k2 = *(const ulonglong2*)&ksm[buf][t][d4 * 4];
                int dq = q * QW + d4 * 4;
                ulonglong2 q0 = *(const ulonglong2*)&qs[0][dq];
                ulonglong2 q1 = *(const ulonglong2*)&qs[1][dq];
                ulonglong2 q2 = *(const ulonglong2*)&qs[2][dq];
                ulonglong2 q3 = *(const ulonglong2*)&qs[3][dq];
                fma2(sca0, k2.x, q0.x); fma2(sca0, k2.y, q0.y);
                fma2(sca1, k2.x, q1.x); fma2(sca1, k2.y, q1.y);
                fma2(sca2, k2.x, q2.x); fma2(sca2, k2.y, q2.y);
                fma2(sca3, k2.x, q3.x); fma2(sca3, k2.y, q3.y);
            }
            __syncthreads();
            buf ^= 1;
        }

        float2 p0 = unpack2(sca0), p1 = unpack2(sca1),
               p2 = unpack2(sca2), p3 = unpack2(sca3);
        float4 e;
        e.x = __expf(p0.x + p0.y); e.y = __expf(p1.x + p1.y);
        e.z = __expf(p2.x + p2.y); e.w = __expf(p3.x + p3.y);
        dent0 += e.x; dent1 += e.y; dent2 += e.z; dent3 += e.w;
        Es4[t] = e;
        __syncthreads();

        // ---- Phase B: V accumulation (packed), rows rg+4j, dims c4*4.. ----
        // 4-row stride = 4*SROW floats = SROW 16B-elements.
        const ulonglong2* V2 = (const ulonglong2*)
            (cV + baseK + (size_t)(t0 + rg) * SROW) + c4;
#pragma unroll 8
        for (int j = 0; j < 32; j++) {
            ulonglong2 v2 = V2[(size_t)j * SROW];        // +4 rows per j
            float4 f = Es4[rg + 4 * j];                  // warp-uniform broadcast
            unsigned long long fx = pack2(f.x, f.x);
            unsigned long long fy = pack2(f.y, f.y);
            unsigned long long fz = pack2(f.z, f.z);
            unsigned long long fw = pack2(f.w, f.w);
            fma2(O0a, fx, v2.x); fma2(O0b, fx, v2.y);
            fma2(O1a, fy, v2.x); fma2(O1b, fy, v2.y);
            fma2(O2a, fz, v2.x); fma2(O2b, fz, v2.y);
            fma2(O3a, fw, v2.x); fma2(O3b, fw, v2.y);
        }
        __syncthreads();
    }

    // unpack accumulators
    float o[GG][4];
    { float2 a = unpack2(O0a), b2 = unpack2(O0b);
      o[0][0]=a.x; o[0][1]=a.y; o[0][2]=b2.x; o[0][3]=b2.y; }
    { float2 a = unpack2(O1a), b2 = unpack2(O1b);
      o[1][0]=a.x; o[1][1]=a.y; o[1][2]=b2.x; o[1][3]=b2.y; }
    { float2 a = unpack2(O2a), b2 = unpack2(O2b);
      o[2][0]=a.x; o[2][1]=a.y; o[2][2]=b2.x; o[2][3]=b2.y; }
    { float2 a = unpack2(O3a), b2 = unpack2(O3b);
      o[3][0]=a.x; o[3][1]=a.y; o[3][2]=b2.x; o[3][3]=b2.y; }

    // Appended row s = P (k_new/v_new): last chunk only
    if (c == NCHUNK - 1) {
        if (t == 0) {
            const float* kn = g_qkv + (size_t)b * ROWS_TOT + NN + kvh * DD;
            float4 e;
            float* ep = &e.x;
#pragma unroll
            for (int g = 0; g < GG; g++) {
                float s0 = 0.f, s1 = 0.f, s2 = 0.f, s3 = 0.f;
                for (int d = 0; d < DD; d += 4) {
                    s0 += qs[g][d + 0] * kn[d + 0];
                    s1 += qs[g][d + 1] * kn[d + 1];
                    s2 += qs[g][d + 2] * kn[d + 2];
                    s3 += qs[g][d + 3] * kn[d + 3];
                }
                ep[g] = __expf(s0 + s1 + s2 + s3);
            }
            Es4[0] = e;
            dent0 += e.x; dent1 += e.y; dent2 += e.z; dent3 += e.w;
        }
        __syncthreads();
        if (rg == 0) {  // exactly one subgroup adds the appended row
            float4 v = *(const float4*)(g_qkv + (size_t)b * ROWS_TOT + NN + KNN
                                        + kvh * DD + c4 * 4);
            float4 f = Es4[0];
#pragma unroll
            for (int d = 0; d < 4; d++) {
                float vd = (&v.x)[d];
                o[0][d] += f.x * vd; o[1][d] += f.y * vd;
                o[2][d] += f.z * vd; o[3][d] += f.w * vd;
            }
        }
        __syncthreads();
    }

    // Denominators: shfl-reduce within warp
    for (int off = 16; off > 0; off >>= 1) {
        dent0 += __shfl_xor_sync(0xffffffffu, dent0, off);
        dent1 += __shfl_xor_sync(0xffffffffu, dent1, off);
        dent2 += __shfl_xor_sync(0xffffffffu, dent2, off);
        dent3 += __shfl_xor_sync(0xffffffffu, dent3, off);
    }
    if (lane == 0) {
        sredW[rg * 4 + 0] = dent0; sredW[rg * 4 + 1] = dent1;
        sredW[rg * 4 + 2] = dent2; sredW[rg * 4 + 3] = dent3;
    }
    int d0 = c4 * 4;
#pragma unroll
    for (int g = 0; g < GG; g++) {
        redO[rg][g][d0+0] = o[g][0]; redO[rg][g][d0+1] = o[g][1];
        redO[rg][g][d0+2] = o[g][2]; redO[rg][g][d0+3] = o[g][3];
    }
    __syncthreads();

    int pb = ((b * KVHH) + kvh) * NCHUNK + c;
    if (t < GG) {
        g_pden[pb][t] = sredW[0 * 4 + t] + sredW[1 * 4 + t]
                      + sredW[2 * 4 + t] + sredW[3 * 4 + t];
    }
#pragma unroll
    for (int g = 0; g < GG; g++) {
        float num = redO[0][g][t] + redO[1][g][t] + redO[2][g][t] + redO[3][g][t];
        g_pnum[pb][g * DD + t] = num;
    }
}

// ---------------------------------------------------------------------------
// 4) Epilogue: sum chunk partials, divide, write [B, N]
// ---------------------------------------------------------------------------
__global__ void attn_epilogue(float* __restrict__ out) {
    int bk = blockIdx.x;   // b*KVHH + kvh
    int t  = threadIdx.x;  // 128
    int b = bk / KVHH, kvh = bk % KVHH;
#pragma unroll
    for (int g = 0; g < GG; g++) {
        float num = 0.f, den = 0.f;
#pragma unroll
        for (int c = 0; c < NCHUNK; c++) {
            int pb = bk * NCHUNK + c;
            num += g_pnum[pb][g * DD + t];
            den += g_pden[pb][g];
        }
        out[(size_t)b * NN + (kvh * GG + g) * DD + t] = num / den;
    }
}

// ---------------------------------------------------------------------------
extern "C" void kernel_launch(void* const* d_in, const int* in_sizes, int n_in,
                              void* d_out, int out_size) {
    const float* X  = (const float*)d_in[0];
    const float* Wq = (const float*)d_in[1];
    const float* Wk = (const float*)d_in[2];
    const float* Wv = (const float*)d_in[3];
    const float* cK = (const float*)d_in[4];
    const float* cV = (const float*)d_in[5];
    float* out = (float*)d_out;

    rms_kernel<<<BB, 256>>>(X);
    qkv_kernel<<<dim3(ROWS_TOT / 128, KSPLIT), 256>>>(Wq, Wk, Wv);
    qkv_reduce<<<(BB * ROWS_TOT) / 256, 256>>>();
    attn_kernel<<<dim3(NCHUNK, KVHH, BB), 128>>>(cK, cV);
    attn_epilogue<<<BB * KVHH, 128>>>(out);
}